// round 17
// baseline (speedup 1.0000x reference)
#include <cuda_runtime.h>
#include <cuda_fp16.h>
#include <cstdint>

#define NN     1024
#define NINP   256
#define NOUTP  256
#define NBAT   8192
#define MAXF   96
#define IMAX   12
#define CAP    1536
#define NBLK   24
#define THREADS 1024

// smem layout (bytes)
#define ZH_OFF    0
#define CP_OFF    101376            // int2[2][1536]  24576
#define PACC_OFF  125952            // float2[32*8][32]  65536
#define IPB_OFF   191488            // int2[2][384]    6144
#define BM_OFF    197632            // int[2][132]      1056
#define ST_OFF    198688            // float[32*66]     8448
#define SMEM_TOT  207136

__device__ int2 g_farp [NN * MAXF];
__device__ int2 g_intra[NN * IMAX];
__device__ int2 g_meta [NN];           // {far count, bits(bias)}
__device__ int  g_icnt [NN];
__device__ int2 g_cpack[NBLK * CAP];
__device__ int  g_bmeta[NBLK][132];    // [0:33) segoff, [33:97) segs, [97:129) nslot
__device__ int  g_rlvl [16 * 32];      // lvl | (icnt<<8)
__device__ int  g_nlev [16];

// ============================================================================
// Build 1: wide W scan. 192 CTAs x 128 thr, one warp per row.
// ============================================================================
__global__ void build_split(const float* __restrict__ W, const float* __restrict__ b)
{
    int row  = NINP + blockIdx.x * 4 + (threadIdx.x >> 5);
    int lane = threadIdx.x & 31;
    int fb   = (row >= NN - NOUTP) ? NN : (row & ~31);
    int m4max = (row + 127) >> 7;
    int fc = 0, ic = 0;
    unsigned lt = (1u << lane) - 1u;
    const float4* wr = reinterpret_cast<const float4*>(W + (size_t)row * NN);
    for (int m = 0; m < m4max; ++m) {
        float4 v = __ldg(wr + m * 32 + lane);
        int c0 = m * 128 + lane * 4;
        #pragma unroll
        for (int q = 0; q < 4; ++q) {
            float wv = (q == 0) ? v.x : (q == 1) ? v.y : (q == 2) ? v.z : v.w;
            int col = c0 + q;
            bool nz = (wv != 0.0f);
            unsigned bf = __ballot_sync(~0u, nz && col <  fb);
            unsigned bi = __ballot_sync(~0u, nz && col >= fb);
            if (nz) {
                if (col < fb) {
                    int p = fc + __popc(bf & lt);
                    if (p < MAXF) g_farp[(size_t)row * MAXF + p] = make_int2(col * 33, __float_as_int(wv));
                } else {
                    int p = ic + __popc(bi & lt);
                    if (p < IMAX) g_intra[(size_t)row * IMAX + p] = make_int2(col * 33, __float_as_int(wv));
                }
            }
            fc += __popc(bf); ic += __popc(bi);
        }
    }
    if (lane == 0) {
        g_meta[row] = make_int2(fc < MAXF ? fc : MAXF, __float_as_int(__ldg(&b[row])));
        g_icnt[row] = ic < IMAX ? ic : IMAX;
    }
}

// ============================================================================
// Build 2: compaction (even-padded rows) + balanced warp segment schedule.
// ============================================================================
__global__ void build_compact()
{
    __shared__ int soff[33];
    __shared__ int scnt[32];

    int blk  = blockIdx.x;
    int base = NINP + blk * 32;
    int tid = threadIdx.x, w = tid >> 5, lane = tid & 31;

    if (w == 0) {
        int cnt  = g_meta[base + lane].x;
        scnt[lane] = cnt;
        int cnt2 = (cnt + 1) & ~1;
        int v = cnt2;
        #pragma unroll
        for (int d = 1; d < 32; d <<= 1) {
            int t = __shfl_up_sync(~0u, v, d);
            if (lane >= d) v += t;
        }
        int excl = v - cnt2;
        soff[lane] = excl;
        if (lane == 31) soff[32] = v < CAP ? v : CAP;
    }
    __syncthreads();

    #pragma unroll
    for (int r = 0; r < 4; ++r) {
        int n = w + 8 * r;
        int off = soff[n], cnt = scnt[n];
        if (off + cnt > CAP) cnt = (CAP - off > 0) ? CAP - off : 0;
        const int2* src = g_farp + (size_t)(base + n) * MAXF;
        int2* dst = g_cpack + (size_t)blk * CAP + off;
        for (int t = lane; t < cnt; t += 32) dst[t] = src[t];
        if (lane == 0 && (cnt & 1)) dst[cnt] = make_int2(0, 0);
    }

    // balanced group schedule (serial on thread 0; 24 CTAs in parallel)
    if (tid == 0) {
        int slotc[32];
        #pragma unroll
        for (int r = 0; r < 32; ++r) slotc[r] = 0;
        int G = soff[32] >> 1;                    // total int4 groups
        int chunk = (G + 31) >> 5; if (chunk == 0) chunk = 1;
        int ns = 0;
        int* bm = g_bmeta[blk];
        for (int w2 = 0; w2 < 32; ++w2) {
            bm[w2] = ns;
            int gs = w2 * chunk;
            int ge = (w2 + 1) * chunk; if (ge > G) ge = G;
            if (gs < ge) {
                for (int r = 0; r < 32; ++r) {
                    int rs = soff[r] >> 1, re2 = soff[r + 1] >> 1;
                    int a = rs > gs ? rs : gs;
                    int e2 = re2 < ge ? re2 : ge;
                    if (a < e2) {
                        int sl = slotc[r]++; if (sl > 7) sl = 7;
                        bm[33 + ns] = r | (sl << 5) | (a << 8) | (e2 << 20);
                        ++ns;
                    }
                }
            }
        }
        bm[32] = ns;
        for (int r = 0; r < 32; ++r) bm[97 + r] = slotc[r] > 8 ? 8 : slotc[r];
    }
}

// ============================================================================
// Build 3: per-node level + per-block level count.
// ============================================================================
__global__ void build_levels()
{
    int blk = blockIdx.x, n = threadIdx.x;
    int base = NINP + blk * 32;
    int row = base + n;
    int ic = g_icnt[row];
    unsigned mymask = 0;
    for (int s = 0; s < ic; ++s) {
        int d = g_intra[(size_t)row * IMAX + s].x / 33 - base;
        if (d >= 0) mymask |= 1u << d;
    }
    int lvl = -1;
    unsigned done = 0;
    for (int it = 0; it < 32; ++it) {
        bool rdy = (lvl < 0) && ((mymask & ~done) == 0);
        unsigned bal = __ballot_sync(~0u, rdy);
        if (rdy) lvl = it;
        done |= bal;
        if (done == 0xffffffffu) break;
    }
    g_rlvl[blk * 32 + n] = lvl | (ic << 8);
    int m = lvl;
    #pragma unroll
    for (int d = 16; d; d >>= 1) m = max(m, __shfl_xor_sync(~0u, m, d));
    if (n == 0) g_nlev[blk] = m + 1;
}

// ============================================================================
// Main: 1024 threads, balanced far segments -> pacc partials -> combine.
// ============================================================================
extern __shared__ char smraw[];

__device__ __forceinline__ float tanhfast(float v) {
    float e = __expf(v + v);
    return 1.0f - __fdividef(2.0f, e + 1.0f);
}

__global__ void __launch_bounds__(THREADS, 1)
dagnn_main(const float* __restrict__ x, float* __restrict__ out)
{
    __half2* zh   = (__half2*)(smraw + ZH_OFF);
    int2*   cpair = (int2*)   (smraw + CP_OFF);
    float2* pacc  = (float2*) (smraw + PACC_OFF);
    int2*   ipb   = (int2*)   (smraw + IPB_OFF);
    int*    bmet  = (int*)    (smraw + BM_OFF);
    float*  st    = (float*)  (smraw + ST_OFF);

    int tid = threadIdx.x, w = tid >> 5, lane = tid & 31;
    int b0 = blockIdx.x * 64;
    __half* zhf = (__half*)zh;

    int2 p0, p1, ib;
    int  aux = 0;

    // ---- prefetch block 0 into regs ----
    {
        const int2* cp = g_cpack;
        p0 = __ldg(cp + tid);
        if (tid < 512)            p1 = __ldg(cp + 1024 + tid);
        if (tid < 384)            ib  = __ldg(&g_intra[(size_t)NINP * IMAX + tid]);
        else if (tid < 513)       aux = __ldg(&g_bmeta[0][tid - 384]);
    }

    // ---- fill z (coalesced LDG -> half STS, stride 66 conflict-free) ----
    #pragma unroll
    for (int it = 0; it < 16; ++it) {
        int t = tid + it * THREADS;
        int n = t & 255, c = t >> 8;
        zhf[n * 66 + c] = __float2half(x[(size_t)(b0 + c) * NINP + n]);
    }

    // ---- commit block 0 into buffer 0 ----
    cpair[tid] = p0;
    if (tid < 512)            cpair[1024 + tid] = p1;
    if (tid < 384)            ipb[tid] = ib;
    else if (tid < 513)       bmet[tid - 384] = aux;

    // ---- prefetch block 1 into regs ----
    {
        const int2* cp = g_cpack + CAP;
        p0 = __ldg(cp + tid);
        if (tid < 512)            p1 = __ldg(cp + 1024 + tid);
        if (tid < 384)            ib  = __ldg(&g_intra[(size_t)(NINP + 32) * IMAX + tid]);
        else if (tid < 513)       aux = __ldg(&g_bmeta[1][tid - 384]);
    }
    __syncthreads();

    for (int k = 0; k < NBLK; ++k) {
        bool hid = (k < 16);
        int buf = k & 1;
        int base = NINP + k * 32;
        const int* bm = bmet + buf * 132;

        // per-warp metadata (uniform; latency hidden under far)
        int lvic = 0, nlev = 0;
        if (hid) { lvic = __ldg(&g_rlvl[k * 32 + w]); nlev = __ldg(&g_nlev[k]); }
        float bias = __int_as_float(__ldg(&g_meta[base + w]).y);

        // ---- balanced far: loop this warp's segments ----
        {
            const int4* p4b = (const int4*)(cpair + buf * CAP);
            int so = bm[w], se = bm[w + 1];
            for (int si = so; si < se; ++si) {
                int sd = bm[33 + si];
                int row  = sd & 31;
                int slot = (sd >> 5) & 7;
                int gs   = (sd >> 8) & 4095;
                int ge   = (sd >> 20) & 4095;
                const int4* p4 = p4b + gs;
                int m = ge - gs;
                float ax = 0.f, ay = 0.f, bx = 0.f, by = 0.f;
                #pragma unroll 4
                for (int j = 0; j < m; ++j) {
                    int4 q = p4[j];
                    float2 za = __half22float2(zh[q.x + lane]);
                    float2 zb = __half22float2(zh[q.z + lane]);
                    float w0 = __int_as_float(q.y), w1 = __int_as_float(q.w);
                    ax = fmaf(w0, za.x, ax); ay = fmaf(w0, za.y, ay);
                    bx = fmaf(w1, zb.x, bx); by = fmaf(w1, zb.y, by);
                }
                pacc[(row * 8 + slot) * 32 + lane] = make_float2(ax + bx, ay + by);
            }
        }

        // ---- commit block k+1 into other buffer (regs already hold it) ----
        if (k + 1 < NBLK) {
            int ob = buf ^ 1;
            int2* cpb = cpair + ob * CAP;
            cpb[tid] = p0;
            if (tid < 512)            cpb[1024 + tid] = p1;
            if (tid < 384)            ipb[ob * 384 + tid] = ib;
            else if (tid < 513)       bmet[ob * 132 + tid - 384] = aux;
        }
        __syncthreads();                          // BAR-F

        // ---- combine row w partials (fixed order -> deterministic) ----
        float vx = bias, vy = bias;
        {
            int ns = bm[97 + w];
            const float2* pr = pacc + (w * 8) * 32 + lane;
            for (int s = 0; s < ns; ++s) {
                float2 pv = pr[s * 32];
                vx += pv.x; vy += pv.y;
            }
        }

        // ---- prefetch block k+2 into regs ----
        if (k + 2 < NBLK) {
            int nb = k + 2;
            const int2* cp = g_cpack + (size_t)nb * CAP;
            p0 = __ldg(cp + tid);
            if (tid < 512)            p1 = __ldg(cp + 1024 + tid);
            if (tid < 384)            { if (nb < 16) ib = __ldg(&g_intra[(size_t)(NINP + nb*32) * IMAX + tid]); }
            else if (tid < 513)       aux = __ldg(&g_bmeta[nb][tid - 384]);
        }

        if (hid) {
            int mylvl = lvic & 255, ic = lvic >> 8;
            for (int L = 0; L < nlev; ++L) {
                if (L == mylvl) {
                    const int2* q = ipb + buf * 384 + w * IMAX;
                    for (int s2 = 0; s2 < ic; ++s2) {
                        int2 p = q[s2];
                        float2 zz = __half22float2(zh[p.x + lane]);
                        float wv = __int_as_float(p.y);
                        vx = fmaf(wv, zz.x, vx);
                        vy = fmaf(wv, zz.y, vy);
                    }
                    zh[(base + w) * 33 + lane] = __floats2half2_rn(tanhfast(vx), tanhfast(vy));
                }
                __syncthreads();
            }
        } else {
            // stage to dedicated st buffer, then coalesced writeout
            *(float2*)&st[w * 66 + 2 * lane] = make_float2(vx, vy);
            __syncthreads();
            int goff = (k - 16) * 32;
            #pragma unroll
            for (int cc = 0; cc < 2; ++cc) {
                int c = 2 * w + cc;
                out[(size_t)(b0 + c) * NOUTP + goff + lane] = st[lane * 66 + c];
            }
        }
    }
}

// ============================================================================
extern "C" void kernel_launch(void* const* d_in, const int* in_sizes, int n_in,
                              void* d_out, int out_size)
{
    const float* x = nullptr; const float* W = nullptr; const float* b = nullptr;
    for (int i = 0; i < n_in; ++i) {
        if      (in_sizes[i] == NBAT * NINP) x = (const float*)d_in[i];
        else if (in_sizes[i] == NN * NN)     W = (const float*)d_in[i];
        else if (in_sizes[i] == NN)          b = (const float*)d_in[i];
    }

    build_split<<<(NN - NINP) / 4, 128>>>(W, b);
    build_compact<<<NBLK, 256>>>();
    build_levels<<<16, 32>>>();

    cudaFuncSetAttribute(dagnn_main,
                         cudaFuncAttributeMaxDynamicSharedMemorySize, SMEM_TOT);
    dagnn_main<<<NBAT / 64, THREADS, SMEM_TOT>>>(x, (float*)d_out);
}